// round 11
// baseline (speedup 1.0000x reference)
#include <cuda_runtime.h>
#include <cuda_bf16.h>
#include <cstdint>
#include <math.h>

#define BB 8
#define CC 256
#define HWN 4096
#define RR 16
#define MQKV 288   // 256 v rows + 16 q rows + 16 k rows
#define MPAD 384   // padded to 3 tiles of 128

// ---------------- scratch (device globals; no allocations) ----------------
__device__ float g_avg[BB*CC];
__device__ float g_mx [BB*CC];
__device__ float g_gate[BB*CC];
__device__ float g_xg[(size_t)BB*CC*HWN];             // fp32 gated input (residual)
__device__ __nv_bfloat16 g_xgt[(size_t)BB*HWN*CC];    // bf16 gated input, transposed [b][n][c]
__device__ __nv_bfloat16 g_wh[MPAD*CC];               // packed bf16 [v;q;k;pad] weights
__device__ float g_bcat[MPAD];
__device__ __nv_bfloat16 g_qt[(size_t)BB*HWN*RR];     // q transposed [b][n][r]
__device__ __nv_bfloat16 g_kt[(size_t)BB*HWN*RR];
__device__ __nv_bfloat16 g_vh[(size_t)BB*CC*HWN];     // V bf16 [b][c][n]

// ---------------- asm helpers ----------------
__device__ __forceinline__ unsigned int sptr(const void* p) {
    return (unsigned int)__cvta_generic_to_shared(p);
}
#define CP16(dst, src) asm volatile("cp.async.cg.shared.global [%0], [%1], 16;\n" :: "r"(dst), "l"(src))
#define CP16P(dst, src) asm volatile("cp.async.cg.shared.global [%0], [%1], 16;\n" :: "r"(sptr(dst)), "l"(src))
#define CP_COMMIT()    asm volatile("cp.async.commit_group;\n")
#define CP_WAIT(n)     asm volatile("cp.async.wait_group %0;\n" :: "n"(n))
#define LDSM4(r0,r1,r2,r3,addr) \
    asm volatile("ldmatrix.sync.aligned.m8n8.x4.shared.b16 {%0,%1,%2,%3}, [%4];\n" \
        : "=r"(r0),"=r"(r1),"=r"(r2),"=r"(r3) : "r"(addr))
#define MMA16816(d,a,b0,b1) \
    asm volatile("mma.sync.aligned.m16n8k16.row.col.f32.bf16.bf16.f32 " \
        "{%0,%1,%2,%3}, {%4,%5,%6,%7}, {%8,%9}, {%0,%1,%2,%3};\n" \
        : "+f"(d[0]),"+f"(d[1]),"+f"(d[2]),"+f"(d[3]) \
        : "r"(a[0]),"r"(a[1]),"r"(a[2]),"r"(a[3]), "r"(b0),"r"(b1))

// ---- fast exp on the FMA pipe (no MUFU): exp(s) = 2^(s*log2e) ----
// round-to-nearest-int trick + degree-3 minimax 2^f on [-0.5, 0.5] (~1e-4 rel err)
__device__ __forceinline__ float fexp(float s) {
    const float L2E = 1.44269504f;
    float t  = fmaf(s, L2E, 12582912.0f);      // 1.5*2^23: forces round-to-nearest int
    float fi = t - 12582912.0f;                // rounded integer part as float
    float f  = fmaf(s, L2E, -fi);              // frac in [-0.5, 0.5]
    float p  = fmaf(f, 0.0558282f, 0.2401397f);
    p = fmaf(f, p, 0.6931472f);
    p = fmaf(f, p, 1.0f);
    int e = (int)fi;
    return p * __int_as_float((e + 127) << 23);
}

// ---------------- 1) avg+max pool over HW per (b,c) ----------------
__global__ __launch_bounds__(256) void k_pool(const float* __restrict__ x) {
    int bc = blockIdx.x;
    const float4* p = (const float4*)(x + (size_t)bc * HWN);
    float s = 0.f, m = -1e30f;
    for (int i = threadIdx.x; i < HWN/4; i += 256) {
        float4 v = p[i];
        s += v.x + v.y + v.z + v.w;
        m = fmaxf(m, fmaxf(fmaxf(v.x, v.y), fmaxf(v.z, v.w)));
    }
    __shared__ float ss[8], sm[8];
    for (int o = 16; o; o >>= 1) {
        s += __shfl_xor_sync(0xffffffffu, s, o);
        m = fmaxf(m, __shfl_xor_sync(0xffffffffu, m, o));
    }
    if ((threadIdx.x & 31) == 0) { ss[threadIdx.x >> 5] = s; sm[threadIdx.x >> 5] = m; }
    __syncthreads();
    if (threadIdx.x == 0) {
        float S = 0.f, M = -1e30f;
        for (int w = 0; w < 8; w++) { S += ss[w]; M = fmaxf(M, sm[w]); }
        g_avg[bc] = S * (1.f / HWN);
        g_mx[bc]  = M;
    }
}

// ---------------- 2) SE gate ----------------
__global__ __launch_bounds__(256) void k_gate(const float* __restrict__ w1,
                                              const float* __restrict__ w2) {
    int b = blockIdx.x, t = threadIdx.x;
    __shared__ float sa[CC], sx[CC], h[RR];
    sa[t] = g_avg[b*CC + t];
    sx[t] = g_mx [b*CC + t];
    __syncthreads();
    if (t < RR) {
        float da = 0.f, dm = 0.f;
        const float* w = w1 + t*CC;
        for (int c = 0; c < CC; c++) { da += w[c]*sa[c]; dm += w[c]*sx[c]; }
        h[t] = fmaxf(da, 0.f) + fmaxf(dm, 0.f);
    }
    __syncthreads();
    float g = 0.f;
    const float* w = w2 + t*RR;
    #pragma unroll
    for (int r = 0; r < RR; r++) g += w[r]*h[r];
    g_gate[b*CC + t] = 1.f / (1.f + __expf(-g));
}

// ---------------- 3) pack [v;q;k] weights -> bf16 (padded), biases fp32 ----------------
__global__ __launch_bounds__(256) void k_wpack(const float* __restrict__ vw,
                                               const float* __restrict__ qw,
                                               const float* __restrict__ kw,
                                               const float* __restrict__ vb,
                                               const float* __restrict__ qb,
                                               const float* __restrict__ kb) {
    int o = blockIdx.x, t = threadIdx.x;
    float val = 0.f, bias = 0.f;
    if (o < CC)            { val = vw[o*CC + t];          bias = vb[o]; }
    else if (o < CC + RR)  { val = qw[(o-CC)*CC + t];     bias = qb[o-CC]; }
    else if (o < MQKV)     { val = kw[(o-CC-RR)*CC + t];  bias = kb[o-CC-RR]; }
    g_wh[o*CC + t] = __float2bfloat16(val);
    if (t == 0) g_bcat[o] = bias;
}

// ---------------- 4) xg (fp32) + transposed bf16 xgt ----------------
__global__ __launch_bounds__(256) void k_xgt(const float* __restrict__ x) {
    int b = blockIdx.z, c0 = blockIdx.y*32, n0 = blockIdx.x*32;
    __shared__ float t[32][33];
    int tid = threadIdx.x;
    int tx = tid & 31, ty = tid >> 5;
    const float* xb  = x    + ((size_t)(b*CC + c0))*HWN + n0;
    float*       xgb = g_xg + ((size_t)(b*CC + c0))*HWN + n0;
    #pragma unroll
    for (int r = ty; r < 32; r += 8) {
        float g = g_gate[b*CC + c0 + r];
        float v = xb[(size_t)r*HWN + tx] * g;
        xgb[(size_t)r*HWN + tx] = v;
        t[r][tx] = v;
    }
    __syncthreads();
    __nv_bfloat16* dst = g_xgt + ((size_t)(b*HWN + n0))*CC + c0;
    int r2 = tid >> 3, ch = (tid & 7) * 4;
    union { __nv_bfloat162 h[2]; uint2 u; } pk;
    pk.h[0] = __floats2bfloat162_rn(t[ch+0][r2], t[ch+1][r2]);
    pk.h[1] = __floats2bfloat162_rn(t[ch+2][r2], t[ch+3][r2]);
    *(uint2*)(dst + (size_t)r2*CC + ch) = pk.u;
}

// ---------------- 5) fused QKV projection, bf16 mma (unchanged, proven) ----------------
__global__ __launch_bounds__(256) void k_qkv() {
    int b  = blockIdx.z;
    int o0 = blockIdx.y * 128;
    int n0 = blockIdx.x * 128;
    __shared__ __align__(16) __nv_bfloat16 As[2][128][40];
    __shared__ __align__(16) __nv_bfloat16 Bs[2][128][40];

    int tid = threadIdx.x, lane = tid & 31, wid = tid >> 5;
    int wm = wid >> 2, wn = wid & 3;

    const __nv_bfloat16* Ab = g_wh + (size_t)o0 * CC;
    const __nv_bfloat16* Bb = g_xgt + ((size_t)(b*HWN) + n0) * CC;

    int lr = tid >> 2;
    int lc = (tid & 3) * 8;

    float acc[4][4][4];
    #pragma unroll
    for (int mi = 0; mi < 4; mi++)
        #pragma unroll
        for (int ni = 0; ni < 4; ni++)
            #pragma unroll
            for (int e = 0; e < 4; e++) acc[mi][ni][e] = 0.f;

    #pragma unroll
    for (int pc = 0; pc < 2; pc++) {
        int k0 = pc * 32;
        CP16P(&As[pc][lr     ][lc], Ab + (size_t)(lr     )*CC + k0 + lc);
        CP16P(&As[pc][lr + 64][lc], Ab + (size_t)(lr + 64)*CC + k0 + lc);
        CP16P(&Bs[pc][lr     ][lc], Bb + (size_t)(lr     )*CC + k0 + lc);
        CP16P(&Bs[pc][lr + 64][lc], Bb + (size_t)(lr + 64)*CC + k0 + lc);
        CP_COMMIT();
    }

    #pragma unroll 1
    for (int it = 0; it < 8; it++) {
        int buf = it & 1;
        if (it == 7) { CP_WAIT(0); } else { CP_WAIT(1); }
        __syncthreads();
        #pragma unroll
        for (int ks = 0; ks < 2; ks++) {
            int k = ks * 16;
            int frow = lane & 15;
            int fcol = k + ((lane >> 4) << 3);
            uint32_t a[4][4];
            #pragma unroll
            for (int mi = 0; mi < 4; mi++) {
                unsigned int ad = sptr(&As[buf][wm*64 + mi*16 + frow][fcol]);
                LDSM4(a[mi][0], a[mi][1], a[mi][2], a[mi][3], ad);
            }
            uint32_t bf[2][4];
            #pragma unroll
            for (int nj = 0; nj < 2; nj++) {
                unsigned int ad = sptr(&Bs[buf][wn*32 + nj*16 + frow][fcol]);
                LDSM4(bf[nj][0], bf[nj][1], bf[nj][2], bf[nj][3], ad);
            }
            #pragma unroll
            for (int mi = 0; mi < 4; mi++)
                #pragma unroll
                for (int ni = 0; ni < 4; ni++) {
                    int nj = ni >> 1, h = ni & 1;
                    MMA16816(acc[mi][ni], a[mi], bf[nj][h], bf[nj][h+2]);
                }
        }
        __syncthreads();
        if (it + 2 < 8) {
            int k0 = (it + 2) * 32;
            CP16P(&As[buf][lr     ][lc], Ab + (size_t)(lr     )*CC + k0 + lc);
            CP16P(&As[buf][lr + 64][lc], Ab + (size_t)(lr + 64)*CC + k0 + lc);
            CP16P(&Bs[buf][lr     ][lc], Bb + (size_t)(lr     )*CC + k0 + lc);
            CP16P(&Bs[buf][lr + 64][lc], Bb + (size_t)(lr + 64)*CC + k0 + lc);
            CP_COMMIT();
        }
    }

    int qr = lane >> 2, qc = (lane & 3) * 2;
    #pragma unroll
    for (int mi = 0; mi < 4; mi++) {
        #pragma unroll
        for (int h = 0; h < 2; h++) {
            int r = o0 + wm*64 + mi*16 + qr + h*8;
            if (r >= MQKV) continue;
            float bias = g_bcat[r];
            if (r < CC) {
                __nv_bfloat16* dst = g_vh + ((size_t)(b*CC + r)) * HWN;
                #pragma unroll
                for (int ni = 0; ni < 4; ni++) {
                    int icol = n0 + wn*32 + ni*8 + qc;
                    *(__nv_bfloat162*)(dst + icol) =
                        __floats2bfloat162_rn(acc[mi][ni][2*h+0] + bias,
                                              acc[mi][ni][2*h+1] + bias);
                }
            } else {
                __nv_bfloat16* dst = (r < CC + RR) ? g_qt : g_kt;
                int rr = (r < CC + RR) ? (r - CC) : (r - CC - RR);
                #pragma unroll
                for (int ni = 0; ni < 4; ni++) {
                    int icol = n0 + wn*32 + ni*8 + qc;
                    dst[((size_t)(b*HWN) + icol    )*RR + rr] = __float2bfloat16(acc[mi][ni][2*h+0] + bias);
                    dst[((size_t)(b*HWN) + icol + 1)*RR + rr] = __float2bfloat16(acc[mi][ni][2*h+1] + bias);
                }
            }
        }
    }
}

// ---------------- 6) FUSED attention (mma.sync): scores+fexp+rowsum+AV+epilogue --------
#define QS_OFF 0
#define KS_OFF 3072
#define ES_OFF 9216
#define VS_OFF 18432
#define RS2_OFF 92160
#define INV_OFF 92672
#define ATTN_SMEM 93184

__global__ __launch_bounds__(256, 1) void k_attn(const float* __restrict__ gamma,
                                                 float* __restrict__ out) {
    extern __shared__ __align__(16) char smx[];
    uint32_t smb = sptr(smx);
    int tid = threadIdx.x, lane = tid & 31, wid = tid >> 5;
    int b = blockIdx.y;
    int i0 = blockIdx.x * 64;

    int qr = lane >> 2, qc = (lane & 3) * 2;
    int frow = lane & 15, fcolh = (lane >> 4) << 3;

    int wm = wid >> 1, wnj = wid & 1;     // score-phase warp grid
    int wc = wid & 3,  wi  = wid >> 2;    // AV-phase warp grid

    if (tid < 128) {
        int row = tid >> 1, half = tid & 1;
        *(uint4*)(smx + QS_OFF + row*48 + half*16) =
            *(const uint4*)(g_qt + ((size_t)(b*HWN) + i0 + row)*RR + half*8);
    }

    #pragma unroll
    for (int pc = 0; pc < 2; pc++) {
        if (tid < 128) {
            int row = tid >> 1, half = tid & 1;
            CP16(smb + KS_OFF + pc*3072 + row*48 + half*16,
                 g_kt + ((size_t)(b*HWN) + pc*64 + row)*RR + half*8);
        }
        #pragma unroll
        for (int v = 0; v < 8; v++) {
            int row = v*32 + (tid >> 3);
            int c16 = tid & 7;
            CP16(smb + VS_OFF + pc*36864 + row*144 + c16*16,
                 g_vh + ((size_t)(b*CC + row))*HWN + pc*64 + c16*8);
        }
        CP_COMMIT();
    }

    float acc[4][4][4];
    #pragma unroll
    for (int mi = 0; mi < 4; mi++)
        #pragma unroll
        for (int ni = 0; ni < 4; ni++)
            #pragma unroll
            for (int e = 0; e < 4; e++) acc[mi][ni][e] = 0.f;
    float rs0 = 0.f, rs1 = 0.f;

    #pragma unroll 1
    for (int jc = 0; jc < 64; jc++) {
        int buf = jc & 1;
        if (jc == 63) { CP_WAIT(0); } else { CP_WAIT(1); }
        __syncthreads();

        // ---- scores: warp (wm, wnj) computes S[16 i x 32 j] ----
        uint32_t aq[4];
        LDSM4(aq[0], aq[1], aq[2], aq[3],
              smb + QS_OFF + (wm*16 + frow)*48 + fcolh*2);
        uint32_t bk[2][4];
        #pragma unroll
        for (int nj = 0; nj < 2; nj++) {
            LDSM4(bk[nj][0], bk[nj][1], bk[nj][2], bk[nj][3],
                  smb + KS_OFF + buf*3072 + (wnj*32 + nj*16 + frow)*48 + fcolh*2);
        }
        float sacc[4][4];
        #pragma unroll
        for (int t = 0; t < 4; t++)
            #pragma unroll
            for (int e = 0; e < 4; e++) sacc[t][e] = 0.f;
        #pragma unroll
        for (int t = 0; t < 4; t++)
            MMA16816(sacc[t], aq, bk[t>>1][t&1], bk[t>>1][(t&1)+2]);

        // ---- fexp (FMA pipe) -> Es smem (bf16), accumulate bf16-rounded row sums ----
        #pragma unroll
        for (int t = 0; t < 4; t++) {
            int col = wnj*32 + t*8 + qc;
            int row = wm*16 + qr;
            __nv_bfloat162 p01 = __floats2bfloat162_rn(fexp(sacc[t][0]), fexp(sacc[t][1]));
            __nv_bfloat162 p23 = __floats2bfloat162_rn(fexp(sacc[t][2]), fexp(sacc[t][3]));
            asm volatile("st.shared.b32 [%0], %1;"
                :: "r"(smb + ES_OFF + row*144 + col*2), "r"(*(uint32_t*)&p01) : "memory");
            asm volatile("st.shared.b32 [%0], %1;"
                :: "r"(smb + ES_OFF + (row+8)*144 + col*2), "r"(*(uint32_t*)&p23) : "memory");
            float2 f01 = __bfloat1622float2(p01);
            float2 f23 = __bfloat1622float2(p23);
            rs0 += f01.x + f01.y;
            rs1 += f23.x + f23.y;
        }
        __syncthreads();

        // ---- AV: warp (wc, wi) does D[64c x 32i] += V[64c x 64j] * E[32i x 64j]^T ----
        #pragma unroll
        for (int ks = 0; ks < 4; ks++) {
            int fcol = ks*16 + fcolh;
            uint32_t av[4][4];
            #pragma unroll
            for (int mi = 0; mi < 4; mi++) {
                LDSM4(av[mi][0], av[mi][1], av[mi][2], av[mi][3],
                      smb + VS_OFF + buf*36864 + (wc*64 + mi*16 + frow)*144 + fcol*2);
            }
            uint32_t be[2][4];
            #pragma unroll
            for (int nj = 0; nj < 2; nj++) {
                LDSM4(be[nj][0], be[nj][1], be[nj][2], be[nj][3],
                      smb + ES_OFF + (wi*32 + nj*16 + frow)*144 + fcol*2);
            }
            #pragma unroll
            for (int mi = 0; mi < 4; mi++)
                #pragma unroll
                for (int ni = 0; ni < 4; ni++)
                    MMA16816(acc[mi][ni], av[mi], be[ni>>1][ni&1], be[ni>>1][(ni&1)+2]);
        }
        __syncthreads();

        // ---- prefetch chunk jc+2 into freed buf ----
        int pf = jc + 2;
        if (pf < 64) {
            if (tid < 128) {
                int row = tid >> 1, half = tid & 1;
                CP16(smb + KS_OFF + buf*3072 + row*48 + half*16,
                     g_kt + ((size_t)(b*HWN) + pf*64 + row)*RR + half*8);
            }
            #pragma unroll
            for (int v = 0; v < 8; v++) {
                int row = v*32 + (tid >> 3);
                int c16 = tid & 7;
                CP16(smb + VS_OFF + buf*36864 + row*144 + c16*16,
                     g_vh + ((size_t)(b*CC + row))*HWN + pf*64 + c16*8);
            }
            CP_COMMIT();
        }
    }

    // ---- row sums: combine j-halves, invert ----
    rs0 += __shfl_xor_sync(0xffffffffu, rs0, 1);
    rs0 += __shfl_xor_sync(0xffffffffu, rs0, 2);
    rs1 += __shfl_xor_sync(0xffffffffu, rs1, 1);
    rs1 += __shfl_xor_sync(0xffffffffu, rs1, 2);
    float* rs2 = (float*)(smx + RS2_OFF);
    float* inv = (float*)(smx + INV_OFF);
    if ((lane & 3) == 0) {
        rs2[wnj*64 + wm*16 + qr    ] = rs0;
        rs2[wnj*64 + wm*16 + qr + 8] = rs1;
    }
    __syncthreads();
    if (tid < 64) inv[tid] = 1.f / (rs2[tid] + rs2[64 + tid]);
    __syncthreads();

    // ---- epilogue: out = gamma * D * inv[i] + xg ----
    float gm = gamma[0];
    #pragma unroll
    for (int ni = 0; ni < 4; ni++) {
        int iloc = wi*32 + ni*8 + qc;
        float inv0 = inv[iloc], inv1 = inv[iloc + 1];
        #pragma unroll
        for (int mi = 0; mi < 4; mi++) {
            #pragma unroll
            for (int h = 0; h < 2; h++) {
                int c = wc*64 + mi*16 + qr + h*8;
                size_t base = ((size_t)(b*CC + c))*HWN + i0 + iloc;
                float2 xgv = *(const float2*)(g_xg + base);
                float2 o;
                o.x = gm * acc[mi][ni][2*h+0] * inv0 + xgv.x;
                o.y = gm * acc[mi][ni][2*h+1] * inv1 + xgv.y;
                *(float2*)(out + base) = o;
            }
        }
    }
}

// ---------------- launch ----------------
extern "C" void kernel_launch(void* const* d_in, const int* in_sizes, int n_in,
                              void* d_out, int out_size) {
    const float* x     = (const float*)d_in[0];
    const float* ca_w1 = (const float*)d_in[1];
    const float* ca_w2 = (const float*)d_in[2];
    const float* q_w   = (const float*)d_in[3];
    const float* q_b   = (const float*)d_in[4];
    const float* k_w   = (const float*)d_in[5];
    const float* k_b   = (const float*)d_in[6];
    const float* v_w   = (const float*)d_in[7];
    const float* v_b   = (const float*)d_in[8];
    const float* gamma = (const float*)d_in[9];
    float* out = (float*)d_out;

    cudaFuncSetAttribute(k_attn, cudaFuncAttributeMaxDynamicSharedMemorySize, ATTN_SMEM);

    k_pool  <<<BB*CC, 256>>>(x);
    k_wpack <<<MPAD, 256>>>(v_w, q_w, k_w, v_b, q_b, k_b);
    k_gate  <<<BB, 256>>>(ca_w1, ca_w2);
    k_xgt   <<<dim3(HWN/32, CC/32, BB), 256>>>(x);
    k_qkv   <<<dim3(HWN/128, MPAD/128, BB), 256>>>();
    k_attn  <<<dim3(HWN/64, BB), 256, ATTN_SMEM>>>(gamma, out);
}

// round 14
// speedup vs baseline: 1.1389x; 1.1389x over previous
#include <cuda_runtime.h>
#include <cuda_bf16.h>
#include <cstdint>
#include <math.h>

#define BB 8
#define CC 256
#define HWN 4096
#define RR 16
#define MQKV 288   // 256 v rows + 16 q rows + 16 k rows
#define MPAD 384   // padded to 3 tiles of 128

// ---------------- scratch (device globals; no allocations) ----------------
__device__ float g_avg[BB*CC];
__device__ float g_mx [BB*CC];
__device__ float g_gate[BB*CC];
__device__ float g_xg[(size_t)BB*CC*HWN];             // fp32 gated input (residual)
__device__ __nv_bfloat16 g_xgt[(size_t)BB*HWN*CC];    // bf16 gated input, transposed [b][n][c]
__device__ __nv_bfloat16 g_wh[MPAD*CC];               // packed bf16 [v;q;k;pad] weights
__device__ float g_bcat[MPAD];
__device__ __nv_bfloat16 g_qt[(size_t)BB*HWN*RR];     // q transposed [b][n][r]
__device__ __nv_bfloat16 g_kt[(size_t)BB*HWN*RR];
__device__ __nv_bfloat16 g_vh[(size_t)BB*CC*HWN];     // V bf16 [b][c][n]

// ---------------- asm helpers ----------------
__device__ __forceinline__ unsigned int sptr(const void* p) {
    return (unsigned int)__cvta_generic_to_shared(p);
}
#define CP16(dst, src) asm volatile("cp.async.cg.shared.global [%0], [%1], 16;\n" :: "r"(dst), "l"(src))
#define CP16P(dst, src) asm volatile("cp.async.cg.shared.global [%0], [%1], 16;\n" :: "r"(sptr(dst)), "l"(src))
#define CP_COMMIT()    asm volatile("cp.async.commit_group;\n")
#define CP_WAIT(n)     asm volatile("cp.async.wait_group %0;\n" :: "n"(n))
#define LDSM4(r0,r1,r2,r3,addr) \
    asm volatile("ldmatrix.sync.aligned.m8n8.x4.shared.b16 {%0,%1,%2,%3}, [%4];\n" \
        : "=r"(r0),"=r"(r1),"=r"(r2),"=r"(r3) : "r"(addr))
#define MMA16816(d,a,b0,b1) \
    asm volatile("mma.sync.aligned.m16n8k16.row.col.f32.bf16.bf16.f32 " \
        "{%0,%1,%2,%3}, {%4,%5,%6,%7}, {%8,%9}, {%0,%1,%2,%3};\n" \
        : "+f"(d[0]),"+f"(d[1]),"+f"(d[2]),"+f"(d[3]) \
        : "r"(a[0]),"r"(a[1]),"r"(a[2]),"r"(a[3]), "r"(b0),"r"(b1))

// ---------------- 1) avg+max pool over HW per (b,c) ----------------
__global__ __launch_bounds__(256) void k_pool(const float* __restrict__ x) {
    int bc = blockIdx.x;
    const float4* p = (const float4*)(x + (size_t)bc * HWN);
    float s = 0.f, m = -1e30f;
    for (int i = threadIdx.x; i < HWN/4; i += 256) {
        float4 v = p[i];
        s += v.x + v.y + v.z + v.w;
        m = fmaxf(m, fmaxf(fmaxf(v.x, v.y), fmaxf(v.z, v.w)));
    }
    __shared__ float ss[8], sm[8];
    for (int o = 16; o; o >>= 1) {
        s += __shfl_xor_sync(0xffffffffu, s, o);
        m = fmaxf(m, __shfl_xor_sync(0xffffffffu, m, o));
    }
    if ((threadIdx.x & 31) == 0) { ss[threadIdx.x >> 5] = s; sm[threadIdx.x >> 5] = m; }
    __syncthreads();
    if (threadIdx.x == 0) {
        float S = 0.f, M = -1e30f;
        for (int w = 0; w < 8; w++) { S += ss[w]; M = fmaxf(M, sm[w]); }
        g_avg[bc] = S * (1.f / HWN);
        g_mx[bc]  = M;
    }
}

// ---------------- 2) SE gate ----------------
__global__ __launch_bounds__(256) void k_gate(const float* __restrict__ w1,
                                              const float* __restrict__ w2) {
    int b = blockIdx.x, t = threadIdx.x;
    __shared__ float sa[CC], sx[CC], h[RR];
    sa[t] = g_avg[b*CC + t];
    sx[t] = g_mx [b*CC + t];
    __syncthreads();
    if (t < RR) {
        float da = 0.f, dm = 0.f;
        const float* w = w1 + t*CC;
        for (int c = 0; c < CC; c++) { da += w[c]*sa[c]; dm += w[c]*sx[c]; }
        h[t] = fmaxf(da, 0.f) + fmaxf(dm, 0.f);
    }
    __syncthreads();
    float g = 0.f;
    const float* w = w2 + t*RR;
    #pragma unroll
    for (int r = 0; r < RR; r++) g += w[r]*h[r];
    g_gate[b*CC + t] = 1.f / (1.f + __expf(-g));
}

// ---------------- 3) pack [v;q;k] weights -> bf16 (padded), biases fp32 ----------------
__global__ __launch_bounds__(256) void k_wpack(const float* __restrict__ vw,
                                               const float* __restrict__ qw,
                                               const float* __restrict__ kw,
                                               const float* __restrict__ vb,
                                               const float* __restrict__ qb,
                                               const float* __restrict__ kb) {
    int o = blockIdx.x, t = threadIdx.x;
    float val = 0.f, bias = 0.f;
    if (o < CC)            { val = vw[o*CC + t];          bias = vb[o]; }
    else if (o < CC + RR)  { val = qw[(o-CC)*CC + t];     bias = qb[o-CC]; }
    else if (o < MQKV)     { val = kw[(o-CC-RR)*CC + t];  bias = kb[o-CC-RR]; }
    g_wh[o*CC + t] = __float2bfloat16(val);
    if (t == 0) g_bcat[o] = bias;
}

// ---------------- 4) xg (fp32) + transposed bf16 xgt ----------------
__global__ __launch_bounds__(256) void k_xgt(const float* __restrict__ x) {
    int b = blockIdx.z, c0 = blockIdx.y*32, n0 = blockIdx.x*32;
    __shared__ float t[32][33];
    int tid = threadIdx.x;
    int tx = tid & 31, ty = tid >> 5;
    const float* xb  = x    + ((size_t)(b*CC + c0))*HWN + n0;
    float*       xgb = g_xg + ((size_t)(b*CC + c0))*HWN + n0;
    #pragma unroll
    for (int r = ty; r < 32; r += 8) {
        float g = g_gate[b*CC + c0 + r];
        float v = xb[(size_t)r*HWN + tx] * g;
        xgb[(size_t)r*HWN + tx] = v;
        t[r][tx] = v;
    }
    __syncthreads();
    __nv_bfloat16* dst = g_xgt + ((size_t)(b*HWN + n0))*CC + c0;
    int r2 = tid >> 3, ch = (tid & 7) * 4;
    union { __nv_bfloat162 h[2]; uint2 u; } pk;
    pk.h[0] = __floats2bfloat162_rn(t[ch+0][r2], t[ch+1][r2]);
    pk.h[1] = __floats2bfloat162_rn(t[ch+2][r2], t[ch+3][r2]);
    *(uint2*)(dst + (size_t)r2*CC + ch) = pk.u;
}

// ---------------- 5) fused QKV projection, bf16 mma (unchanged, proven) ----------------
__global__ __launch_bounds__(256) void k_qkv() {
    int b  = blockIdx.z;
    int o0 = blockIdx.y * 128;
    int n0 = blockIdx.x * 128;
    __shared__ __align__(16) __nv_bfloat16 As[2][128][40];
    __shared__ __align__(16) __nv_bfloat16 Bs[2][128][40];

    int tid = threadIdx.x, lane = tid & 31, wid = tid >> 5;
    int wm = wid >> 2, wn = wid & 3;

    const __nv_bfloat16* Ab = g_wh + (size_t)o0 * CC;
    const __nv_bfloat16* Bb = g_xgt + ((size_t)(b*HWN) + n0) * CC;

    int lr = tid >> 2;
    int lc = (tid & 3) * 8;

    float acc[4][4][4];
    #pragma unroll
    for (int mi = 0; mi < 4; mi++)
        #pragma unroll
        for (int ni = 0; ni < 4; ni++)
            #pragma unroll
            for (int e = 0; e < 4; e++) acc[mi][ni][e] = 0.f;

    #pragma unroll
    for (int pc = 0; pc < 2; pc++) {
        int k0 = pc * 32;
        CP16P(&As[pc][lr     ][lc], Ab + (size_t)(lr     )*CC + k0 + lc);
        CP16P(&As[pc][lr + 64][lc], Ab + (size_t)(lr + 64)*CC + k0 + lc);
        CP16P(&Bs[pc][lr     ][lc], Bb + (size_t)(lr     )*CC + k0 + lc);
        CP16P(&Bs[pc][lr + 64][lc], Bb + (size_t)(lr + 64)*CC + k0 + lc);
        CP_COMMIT();
    }

    #pragma unroll 1
    for (int it = 0; it < 8; it++) {
        int buf = it & 1;
        if (it == 7) { CP_WAIT(0); } else { CP_WAIT(1); }
        __syncthreads();
        #pragma unroll
        for (int ks = 0; ks < 2; ks++) {
            int k = ks * 16;
            int frow = lane & 15;
            int fcol = k + ((lane >> 4) << 3);
            uint32_t a[4][4];
            #pragma unroll
            for (int mi = 0; mi < 4; mi++) {
                unsigned int ad = sptr(&As[buf][wm*64 + mi*16 + frow][fcol]);
                LDSM4(a[mi][0], a[mi][1], a[mi][2], a[mi][3], ad);
            }
            uint32_t bf[2][4];
            #pragma unroll
            for (int nj = 0; nj < 2; nj++) {
                unsigned int ad = sptr(&Bs[buf][wn*32 + nj*16 + frow][fcol]);
                LDSM4(bf[nj][0], bf[nj][1], bf[nj][2], bf[nj][3], ad);
            }
            #pragma unroll
            for (int mi = 0; mi < 4; mi++)
                #pragma unroll
                for (int ni = 0; ni < 4; ni++) {
                    int nj = ni >> 1, h = ni & 1;
                    MMA16816(acc[mi][ni], a[mi], bf[nj][h], bf[nj][h+2]);
                }
        }
        __syncthreads();
        if (it + 2 < 8) {
            int k0 = (it + 2) * 32;
            CP16P(&As[buf][lr     ][lc], Ab + (size_t)(lr     )*CC + k0 + lc);
            CP16P(&As[buf][lr + 64][lc], Ab + (size_t)(lr + 64)*CC + k0 + lc);
            CP16P(&Bs[buf][lr     ][lc], Bb + (size_t)(lr     )*CC + k0 + lc);
            CP16P(&Bs[buf][lr + 64][lc], Bb + (size_t)(lr + 64)*CC + k0 + lc);
            CP_COMMIT();
        }
    }

    int qr = lane >> 2, qc = (lane & 3) * 2;
    #pragma unroll
    for (int mi = 0; mi < 4; mi++) {
        #pragma unroll
        for (int h = 0; h < 2; h++) {
            int r = o0 + wm*64 + mi*16 + qr + h*8;
            if (r >= MQKV) continue;
            float bias = g_bcat[r];
            if (r < CC) {
                __nv_bfloat16* dst = g_vh + ((size_t)(b*CC + r)) * HWN;
                #pragma unroll
                for (int ni = 0; ni < 4; ni++) {
                    int icol = n0 + wn*32 + ni*8 + qc;
                    *(__nv_bfloat162*)(dst + icol) =
                        __floats2bfloat162_rn(acc[mi][ni][2*h+0] + bias,
                                              acc[mi][ni][2*h+1] + bias);
                }
            } else {
                __nv_bfloat16* dst = (r < CC + RR) ? g_qt : g_kt;
                int rr = (r < CC + RR) ? (r - CC) : (r - CC - RR);
                #pragma unroll
                for (int ni = 0; ni < 4; ni++) {
                    int icol = n0 + wn*32 + ni*8 + qc;
                    dst[((size_t)(b*HWN) + icol    )*RR + rr] = __float2bfloat16(acc[mi][ni][2*h+0] + bias);
                    dst[((size_t)(b*HWN) + icol + 1)*RR + rr] = __float2bfloat16(acc[mi][ni][2*h+1] + bias);
                }
            }
        }
    }
}

// ---------------- 6) FUSED attention, occupancy 2: j-chunk 32, 52 KB smem --------------
// One CTA per (64-row i-tile, batch); 2 CTAs/SM overlap each other's exp/sync phases.
// smem layout (bytes), 80B rows are bank-conflict-free for ldmatrix:
//   Qs  @ 0     : 64 x 48B                 = 3072
//   Ks  @ 3072  : 2 bufs x 32 x 48B        = 3072
//   Es  @ 6144  : 64 x 80B                 = 5120
//   Vs  @ 11264 : 2 bufs x 256 x 80B       = 40960
//   rs2 @ 52224 : 2 x 64 fp32              = 512
//   inv @ 52736 : 64 fp32                  = 256
#define QS_OFF 0
#define KS_OFF 3072
#define ES_OFF 6144
#define VS_OFF 11264
#define RS2_OFF 52224
#define INV_OFF 52736
#define ATTN_SMEM 52992
#define NCHUNK 128           // 4096 / 32

__global__ __launch_bounds__(256, 2) void k_attn(const float* __restrict__ gamma,
                                                 float* __restrict__ out) {
    extern __shared__ __align__(16) char smx[];
    uint32_t smb = sptr(smx);
    int tid = threadIdx.x, lane = tid & 31, wid = tid >> 5;
    int b = blockIdx.y;
    int i0 = blockIdx.x * 64;

    int qr = lane >> 2, qc = (lane & 3) * 2;
    int frow = lane & 15, fcolh = (lane >> 4) << 3;

    int wm = wid >> 1, wnj = wid & 1;     // score phase: 4 i-groups x 2 j-halves(16)
    int wc = wid & 3,  wi  = wid >> 2;    // AV phase: 4 c-groups(64) x 2 i-halves(32)

    if (tid < 128) {
        int row = tid >> 1, half = tid & 1;
        *(uint4*)(smx + QS_OFF + row*48 + half*16) =
            *(const uint4*)(g_qt + ((size_t)(b*HWN) + i0 + row)*RR + half*8);
    }

    // prologue: K + V for chunks 0, 1 (32 j each)
    #pragma unroll
    for (int pc = 0; pc < 2; pc++) {
        if (tid < 64) {
            int row = tid >> 1, half = tid & 1;
            CP16(smb + KS_OFF + pc*1536 + row*48 + half*16,
                 g_kt + ((size_t)(b*HWN) + pc*32 + row)*RR + half*8);
        }
        #pragma unroll
        for (int v = 0; v < 4; v++) {
            int row = v*64 + (tid >> 2);
            int c16 = tid & 3;
            CP16(smb + VS_OFF + pc*20480 + row*80 + c16*16,
                 g_vh + ((size_t)(b*CC + row))*HWN + pc*32 + c16*8);
        }
        CP_COMMIT();
    }

    float acc[4][4][4];
    #pragma unroll
    for (int mi = 0; mi < 4; mi++)
        #pragma unroll
        for (int ni = 0; ni < 4; ni++)
            #pragma unroll
            for (int e = 0; e < 4; e++) acc[mi][ni][e] = 0.f;
    float rs0 = 0.f, rs1 = 0.f;

    #pragma unroll 1
    for (int jc = 0; jc < NCHUNK; jc++) {
        int buf = jc & 1;
        if (jc == NCHUNK-1) { CP_WAIT(0); } else { CP_WAIT(1); }
        __syncthreads();

        // ---- scores: warp (wm, wnj) computes S[16 i x 16 j] ----
        uint32_t aq[4];
        LDSM4(aq[0], aq[1], aq[2], aq[3],
              smb + QS_OFF + (wm*16 + frow)*48 + fcolh*2);
        uint32_t bk[4];
        LDSM4(bk[0], bk[1], bk[2], bk[3],
              smb + KS_OFF + buf*1536 + (wnj*16 + frow)*48 + fcolh*2);
        float sacc[2][4];
        #pragma unroll
        for (int t = 0; t < 2; t++)
            #pragma unroll
            for (int e = 0; e < 4; e++) sacc[t][e] = 0.f;
        #pragma unroll
        for (int t = 0; t < 2; t++)
            MMA16816(sacc[t], aq, bk[t], bk[t+2]);

        // ---- exp -> Es smem (bf16), accumulate bf16-rounded row sums ----
        #pragma unroll
        for (int t = 0; t < 2; t++) {
            int col = wnj*16 + t*8 + qc;
            int row = wm*16 + qr;
            __nv_bfloat162 p01 = __floats2bfloat162_rn(__expf(sacc[t][0]), __expf(sacc[t][1]));
            __nv_bfloat162 p23 = __floats2bfloat162_rn(__expf(sacc[t][2]), __expf(sacc[t][3]));
            asm volatile("st.shared.b32 [%0], %1;"
                :: "r"(smb + ES_OFF + row*80 + col*2), "r"(*(uint32_t*)&p01) : "memory");
            asm volatile("st.shared.b32 [%0], %1;"
                :: "r"(smb + ES_OFF + (row+8)*80 + col*2), "r"(*(uint32_t*)&p23) : "memory");
            float2 f01 = __bfloat1622float2(p01);
            float2 f23 = __bfloat1622float2(p23);
            rs0 += f01.x + f01.y;
            rs1 += f23.x + f23.y;
        }
        __syncthreads();

        // ---- AV: warp (wc, wi) does D[64c x 32i] += V[64c x 32j] * E[32i x 32j]^T ----
        #pragma unroll
        for (int ks = 0; ks < 2; ks++) {
            int fcol = ks*16 + fcolh;
            uint32_t av[4][4];
            #pragma unroll
            for (int mi = 0; mi < 4; mi++) {
                LDSM4(av[mi][0], av[mi][1], av[mi][2], av[mi][3],
                      smb + VS_OFF + buf*20480 + (wc*64 + mi*16 + frow)*80 + fcol*2);
            }
            uint32_t be[2][4];
            #pragma unroll
            for (int nj = 0; nj < 2; nj++) {
                LDSM4(be[nj][0], be[nj][1], be[nj][2], be[nj][3],
                      smb + ES_OFF + (wi*32 + nj*16 + frow)*80 + fcol*2);
            }
            #pragma unroll
            for (int mi = 0; mi < 4; mi++)
                #pragma unroll
                for (int ni = 0; ni < 4; ni++)
                    MMA16816(acc[mi][ni], av[mi], be[ni>>1][ni&1], be[ni>>1][(ni&1)+2]);
        }
        __syncthreads();

        // ---- prefetch chunk jc+2 into freed buf ----
        int pf = jc + 2;
        if (pf < NCHUNK) {
            if (tid < 64) {
                int row = tid >> 1, half = tid & 1;
                CP16(smb + KS_OFF + buf*1536 + row*48 + half*16,
                     g_kt + ((size_t)(b*HWN) + pf*32 + row)*RR + half*8);
            }
            #pragma unroll
            for (int v = 0; v < 4; v++) {
                int row = v*64 + (tid >> 2);
                int c16 = tid & 3;
                CP16(smb + VS_OFF + buf*20480 + row*80 + c16*16,
                     g_vh + ((size_t)(b*CC + row))*HWN + pf*32 + c16*8);
            }
            CP_COMMIT();
        }
    }

    // ---- row sums: combine j-halves, invert ----
    rs0 += __shfl_xor_sync(0xffffffffu, rs0, 1);
    rs0 += __shfl_xor_sync(0xffffffffu, rs0, 2);
    rs1 += __shfl_xor_sync(0xffffffffu, rs1, 1);
    rs1 += __shfl_xor_sync(0xffffffffu, rs1, 2);
    float* rs2 = (float*)(smx + RS2_OFF);
    float* inv = (float*)(smx + INV_OFF);
    if ((lane & 3) == 0) {
        rs2[wnj*64 + wm*16 + qr    ] = rs0;
        rs2[wnj*64 + wm*16 + qr + 8] = rs1;
    }
    __syncthreads();
    if (tid < 64) inv[tid] = 1.f / (rs2[tid] + rs2[64 + tid]);
    __syncthreads();

    // ---- epilogue: out = gamma * D * inv[i] + xg ----
    float gm = gamma[0];
    #pragma unroll
    for (int ni = 0; ni < 4; ni++) {
        int iloc = wi*32 + ni*8 + qc;
        float inv0 = inv[iloc], inv1 = inv[iloc + 1];
        #pragma unroll
        for (int mi = 0; mi < 4; mi++) {
            #pragma unroll
            for (int h = 0; h < 2; h++) {
                int c = wc*64 + mi*16 + qr + h*8;
                size_t base = ((size_t)(b*CC + c))*HWN + i0 + iloc;
                float2 xgv = *(const float2*)(g_xg + base);
                float2 o;
                o.x = gm * acc[mi][ni][2*h+0] * inv0 + xgv.x;
                o.y = gm * acc[mi][ni][2*h+1] * inv1 + xgv.y;
                *(float2*)(out + base) = o;
            }
        }
    }
}

// ---------------- launch ----------------
extern "C" void kernel_launch(void* const* d_in, const int* in_sizes, int n_in,
                              void* d_out, int out_size) {
    const float* x     = (const float*)d_in[0];
    const float* ca_w1 = (const float*)d_in[1];
    const float* ca_w2 = (const float*)d_in[2];
    const float* q_w   = (const float*)d_in[3];
    const float* q_b   = (const float*)d_in[4];
    const float* k_w   = (const float*)d_in[5];
    const float* k_b   = (const float*)d_in[6];
    const float* v_w   = (const float*)d_in[7];
    const float* v_b   = (const float*)d_in[8];
    const float* gamma = (const float*)d_in[9];
    float* out = (float*)d_out;

    cudaFuncSetAttribute(k_attn, cudaFuncAttributeMaxDynamicSharedMemorySize, ATTN_SMEM);

    k_pool  <<<BB*CC, 256>>>(x);
    k_wpack <<<MPAD, 256>>>(v_w, q_w, k_w, v_b, q_b, k_b);
    k_gate  <<<BB, 256>>>(ca_w1, ca_w2);
    k_xgt   <<<dim3(HWN/32, CC/32, BB), 256>>>(x);
    k_qkv   <<<dim3(HWN/128, MPAD/128, BB), 256>>>();
    k_attn  <<<dim3(HWN/64, BB), 256, ATTN_SMEM>>>(gamma, out);
}

// round 15
// speedup vs baseline: 1.2855x; 1.1287x over previous
#include <cuda_runtime.h>
#include <cuda_bf16.h>
#include <cstdint>
#include <math.h>

#define BB 8
#define CC 256
#define HWN 4096
#define RR 16
#define MQKV 288   // 256 v rows + 16 q rows + 16 k rows
#define MPAD 384   // padded to 3 tiles of 128

// ---------------- scratch (device globals; no allocations) ----------------
__device__ float g_avg[BB*CC];
__device__ float g_mx [BB*CC];
__device__ float g_gate[BB*CC];
__device__ float g_xg[(size_t)BB*CC*HWN];             // fp32 gated input (residual)
__device__ __nv_bfloat16 g_xgt[(size_t)BB*HWN*CC];    // bf16 gated input, transposed [b][n][c]
__device__ __nv_bfloat16 g_wh[MPAD*CC];               // packed bf16 [v;q;k;pad] weights
__device__ float g_bcat[MPAD];
__device__ __nv_bfloat16 g_qt[(size_t)BB*HWN*RR];     // q transposed [b][n][r]
__device__ __nv_bfloat16 g_kt[(size_t)BB*HWN*RR];
__device__ uint8_t g_v8[(size_t)BB*CC*HWN];           // V in fp8 e4m3 [b][c][n]

// ---------------- asm helpers ----------------
__device__ __forceinline__ unsigned int sptr(const void* p) {
    return (unsigned int)__cvta_generic_to_shared(p);
}
#define CP16(dst, src) asm volatile("cp.async.cg.shared.global [%0], [%1], 16;\n" :: "r"(dst), "l"(src))
#define CP16P(dst, src) asm volatile("cp.async.cg.shared.global [%0], [%1], 16;\n" :: "r"(sptr(dst)), "l"(src))
#define CP_COMMIT()    asm volatile("cp.async.commit_group;\n")
#define CP_WAIT(n)     asm volatile("cp.async.wait_group %0;\n" :: "n"(n))
#define LDSM4(r0,r1,r2,r3,addr) \
    asm volatile("ldmatrix.sync.aligned.m8n8.x4.shared.b16 {%0,%1,%2,%3}, [%4];\n" \
        : "=r"(r0),"=r"(r1),"=r"(r2),"=r"(r3) : "r"(addr))
#define MMA16816(d,a,b0,b1) \
    asm volatile("mma.sync.aligned.m16n8k16.row.col.f32.bf16.bf16.f32 " \
        "{%0,%1,%2,%3}, {%4,%5,%6,%7}, {%8,%9}, {%0,%1,%2,%3};\n" \
        : "+f"(d[0]),"+f"(d[1]),"+f"(d[2]),"+f"(d[3]) \
        : "r"(a[0]),"r"(a[1]),"r"(a[2]),"r"(a[3]), "r"(b0),"r"(b1))
#define MMAFP8(d,a,b0,b1) \
    asm volatile("mma.sync.aligned.m16n8k32.row.col.f32.e4m3.e4m3.f32 " \
        "{%0,%1,%2,%3}, {%4,%5,%6,%7}, {%8,%9}, {%0,%1,%2,%3};\n" \
        : "+f"(d[0]),"+f"(d[1]),"+f"(d[2]),"+f"(d[3]) \
        : "r"(a[0]),"r"(a[1]),"r"(a[2]),"r"(a[3]), "r"(b0),"r"(b1))

// pack two f32 -> e4m3x2 (lo at low byte), decode back via f16x2
__device__ __forceinline__ uint16_t pk_e4m3(float lo, float hi) {
    uint16_t r;
    asm("cvt.rn.satfinite.e4m3x2.f32 %0, %1, %2;" : "=h"(r) : "f"(hi), "f"(lo));
    return r;
}
__device__ __forceinline__ float2 de_e4m3(uint16_t h) {
    uint32_t hf;
    asm("cvt.rn.f16x2.e4m3x2 %0, %1;" : "=r"(hf) : "h"(h));
    __half2 h2 = *(__half2*)&hf;
    return __half22float2(h2);
}

// ---------------- 1) avg+max pool over HW per (b,c) ----------------
__global__ __launch_bounds__(256) void k_pool(const float* __restrict__ x) {
    int bc = blockIdx.x;
    const float4* p = (const float4*)(x + (size_t)bc * HWN);
    float s = 0.f, m = -1e30f;
    for (int i = threadIdx.x; i < HWN/4; i += 256) {
        float4 v = p[i];
        s += v.x + v.y + v.z + v.w;
        m = fmaxf(m, fmaxf(fmaxf(v.x, v.y), fmaxf(v.z, v.w)));
    }
    __shared__ float ss[8], sm[8];
    for (int o = 16; o; o >>= 1) {
        s += __shfl_xor_sync(0xffffffffu, s, o);
        m = fmaxf(m, __shfl_xor_sync(0xffffffffu, m, o));
    }
    if ((threadIdx.x & 31) == 0) { ss[threadIdx.x >> 5] = s; sm[threadIdx.x >> 5] = m; }
    __syncthreads();
    if (threadIdx.x == 0) {
        float S = 0.f, M = -1e30f;
        for (int w = 0; w < 8; w++) { S += ss[w]; M = fmaxf(M, sm[w]); }
        g_avg[bc] = S * (1.f / HWN);
        g_mx[bc]  = M;
    }
}

// ---------------- 2) SE gate ----------------
__global__ __launch_bounds__(256) void k_gate(const float* __restrict__ w1,
                                              const float* __restrict__ w2) {
    int b = blockIdx.x, t = threadIdx.x;
    __shared__ float sa[CC], sx[CC], h[RR];
    sa[t] = g_avg[b*CC + t];
    sx[t] = g_mx [b*CC + t];
    __syncthreads();
    if (t < RR) {
        float da = 0.f, dm = 0.f;
        const float* w = w1 + t*CC;
        for (int c = 0; c < CC; c++) { da += w[c]*sa[c]; dm += w[c]*sx[c]; }
        h[t] = fmaxf(da, 0.f) + fmaxf(dm, 0.f);
    }
    __syncthreads();
    float g = 0.f;
    const float* w = w2 + t*RR;
    #pragma unroll
    for (int r = 0; r < RR; r++) g += w[r]*h[r];
    g_gate[b*CC + t] = 1.f / (1.f + __expf(-g));
}

// ---------------- 3) pack [v;q;k] weights -> bf16 (padded), biases fp32 ----------------
__global__ __launch_bounds__(256) void k_wpack(const float* __restrict__ vw,
                                               const float* __restrict__ qw,
                                               const float* __restrict__ kw,
                                               const float* __restrict__ vb,
                                               const float* __restrict__ qb,
                                               const float* __restrict__ kb) {
    int o = blockIdx.x, t = threadIdx.x;
    float val = 0.f, bias = 0.f;
    if (o < CC)            { val = vw[o*CC + t];          bias = vb[o]; }
    else if (o < CC + RR)  { val = qw[(o-CC)*CC + t];     bias = qb[o-CC]; }
    else if (o < MQKV)     { val = kw[(o-CC-RR)*CC + t];  bias = kb[o-CC-RR]; }
    g_wh[o*CC + t] = __float2bfloat16(val);
    if (t == 0) g_bcat[o] = bias;
}

// ---------------- 4) xg (fp32) + transposed bf16 xgt ----------------
__global__ __launch_bounds__(256) void k_xgt(const float* __restrict__ x) {
    int b = blockIdx.z, c0 = blockIdx.y*32, n0 = blockIdx.x*32;
    __shared__ float t[32][33];
    int tid = threadIdx.x;
    int tx = tid & 31, ty = tid >> 5;
    const float* xb  = x    + ((size_t)(b*CC + c0))*HWN + n0;
    float*       xgb = g_xg + ((size_t)(b*CC + c0))*HWN + n0;
    #pragma unroll
    for (int r = ty; r < 32; r += 8) {
        float g = g_gate[b*CC + c0 + r];
        float v = xb[(size_t)r*HWN + tx] * g;
        xgb[(size_t)r*HWN + tx] = v;
        t[r][tx] = v;
    }
    __syncthreads();
    __nv_bfloat16* dst = g_xgt + ((size_t)(b*HWN + n0))*CC + c0;
    int r2 = tid >> 3, ch = (tid & 7) * 4;
    union { __nv_bfloat162 h[2]; uint2 u; } pk;
    pk.h[0] = __floats2bfloat162_rn(t[ch+0][r2], t[ch+1][r2]);
    pk.h[1] = __floats2bfloat162_rn(t[ch+2][r2], t[ch+3][r2]);
    *(uint2*)(dst + (size_t)r2*CC + ch) = pk.u;
}

// ---------------- 5) fused QKV projection, bf16 mma; V out in fp8 ----------------
__global__ __launch_bounds__(256) void k_qkv() {
    int b  = blockIdx.z;
    int o0 = blockIdx.y * 128;
    int n0 = blockIdx.x * 128;
    __shared__ __align__(16) __nv_bfloat16 As[2][128][40];
    __shared__ __align__(16) __nv_bfloat16 Bs[2][128][40];

    int tid = threadIdx.x, lane = tid & 31, wid = tid >> 5;
    int wm = wid >> 2, wn = wid & 3;

    const __nv_bfloat16* Ab = g_wh + (size_t)o0 * CC;
    const __nv_bfloat16* Bb = g_xgt + ((size_t)(b*HWN) + n0) * CC;

    int lr = tid >> 2;
    int lc = (tid & 3) * 8;

    float acc[4][4][4];
    #pragma unroll
    for (int mi = 0; mi < 4; mi++)
        #pragma unroll
        for (int ni = 0; ni < 4; ni++)
            #pragma unroll
            for (int e = 0; e < 4; e++) acc[mi][ni][e] = 0.f;

    #pragma unroll
    for (int pc = 0; pc < 2; pc++) {
        int k0 = pc * 32;
        CP16P(&As[pc][lr     ][lc], Ab + (size_t)(lr     )*CC + k0 + lc);
        CP16P(&As[pc][lr + 64][lc], Ab + (size_t)(lr + 64)*CC + k0 + lc);
        CP16P(&Bs[pc][lr     ][lc], Bb + (size_t)(lr     )*CC + k0 + lc);
        CP16P(&Bs[pc][lr + 64][lc], Bb + (size_t)(lr + 64)*CC + k0 + lc);
        CP_COMMIT();
    }

    #pragma unroll 1
    for (int it = 0; it < 8; it++) {
        int buf = it & 1;
        if (it == 7) { CP_WAIT(0); } else { CP_WAIT(1); }
        __syncthreads();
        #pragma unroll
        for (int ks = 0; ks < 2; ks++) {
            int k = ks * 16;
            int frow = lane & 15;
            int fcol = k + ((lane >> 4) << 3);
            uint32_t a[4][4];
            #pragma unroll
            for (int mi = 0; mi < 4; mi++) {
                unsigned int ad = sptr(&As[buf][wm*64 + mi*16 + frow][fcol]);
                LDSM4(a[mi][0], a[mi][1], a[mi][2], a[mi][3], ad);
            }
            uint32_t bf[2][4];
            #pragma unroll
            for (int nj = 0; nj < 2; nj++) {
                unsigned int ad = sptr(&Bs[buf][wn*32 + nj*16 + frow][fcol]);
                LDSM4(bf[nj][0], bf[nj][1], bf[nj][2], bf[nj][3], ad);
            }
            #pragma unroll
            for (int mi = 0; mi < 4; mi++)
                #pragma unroll
                for (int ni = 0; ni < 4; ni++) {
                    int nj = ni >> 1, h = ni & 1;
                    MMA16816(acc[mi][ni], a[mi], bf[nj][h], bf[nj][h+2]);
                }
        }
        __syncthreads();
        if (it + 2 < 8) {
            int k0 = (it + 2) * 32;
            CP16P(&As[buf][lr     ][lc], Ab + (size_t)(lr     )*CC + k0 + lc);
            CP16P(&As[buf][lr + 64][lc], Ab + (size_t)(lr + 64)*CC + k0 + lc);
            CP16P(&Bs[buf][lr     ][lc], Bb + (size_t)(lr     )*CC + k0 + lc);
            CP16P(&Bs[buf][lr + 64][lc], Bb + (size_t)(lr + 64)*CC + k0 + lc);
            CP_COMMIT();
        }
    }

    int qr = lane >> 2, qc = (lane & 3) * 2;
    #pragma unroll
    for (int mi = 0; mi < 4; mi++) {
        #pragma unroll
        for (int h = 0; h < 2; h++) {
            int r = o0 + wm*64 + mi*16 + qr + h*8;
            if (r >= MQKV) continue;
            float bias = g_bcat[r];
            if (r < CC) {
                uint8_t* dst = g_v8 + ((size_t)(b*CC + r)) * HWN;
                #pragma unroll
                for (int ni = 0; ni < 4; ni++) {
                    int icol = n0 + wn*32 + ni*8 + qc;
                    *(uint16_t*)(dst + icol) =
                        pk_e4m3(acc[mi][ni][2*h+0] + bias, acc[mi][ni][2*h+1] + bias);
                }
            } else {
                __nv_bfloat16* dst = (r < CC + RR) ? g_qt : g_kt;
                int rr = (r < CC + RR) ? (r - CC) : (r - CC - RR);
                #pragma unroll
                for (int ni = 0; ni < 4; ni++) {
                    int icol = n0 + wn*32 + ni*8 + qc;
                    dst[((size_t)(b*HWN) + icol    )*RR + rr] = __float2bfloat16(acc[mi][ni][2*h+0] + bias);
                    dst[((size_t)(b*HWN) + icol + 1)*RR + rr] = __float2bfloat16(acc[mi][ni][2*h+1] + bias);
                }
            }
        }
    }
}

// ---------------- 6) FUSED attention, fp8 AV, chunk 64, occupancy 2 --------------------
// One CTA per (64-row i-tile, batch). scores bf16 mma; E quantized e4m3 (scale e^-3
// cancels in softmax); AV via mma.m16n8k32.e4m3 (2x MACs/instr). Row sums from the
// DECODED fp8 values => normalization exactly consistent.
// smem (80B/48B strides conflict-free for ldmatrix):
//   Qs  @ 0     : 64 x 48B            = 3072
//   Ks  @ 3072  : 2 x 64 x 48B        = 6144
//   Es  @ 9216  : 64 x 80B (fp8)      = 5120
//   Vs  @ 14336 : 2 x 256 x 80B (fp8) = 40960
//   rs2 @ 55296 : 2 x 64 f32          = 512
//   inv @ 55808 : 64 f32              = 256
#define QS_OFF 0
#define KS_OFF 3072
#define ES_OFF 9216
#define VS_OFF 14336
#define RS2_OFF 55296
#define INV_OFF 55808
#define ATTN_SMEM 56064
#define NCHUNK 64            // 4096 / 64

__global__ __launch_bounds__(256, 2) void k_attn(const float* __restrict__ gamma,
                                                 float* __restrict__ out) {
    extern __shared__ __align__(16) char smx[];
    uint32_t smb = sptr(smx);
    int tid = threadIdx.x, lane = tid & 31, wid = tid >> 5;
    int b = blockIdx.y;
    int i0 = blockIdx.x * 64;

    int qr = lane >> 2, qc = (lane & 3) * 2;
    int frow = lane & 15, fcolh = (lane >> 4) << 3;

    int wm = wid >> 1, wnj = wid & 1;     // score phase: 4 i-groups(16) x 2 j-halves(32)
    int wc = wid & 3,  wi  = wid >> 2;    // AV phase: 4 c-groups(64) x 2 i-halves(32)

    if (tid < 128) {
        int row = tid >> 1, half = tid & 1;
        *(uint4*)(smx + QS_OFF + row*48 + half*16) =
            *(const uint4*)(g_qt + ((size_t)(b*HWN) + i0 + row)*RR + half*8);
    }

    // prologue: K + V for chunks 0, 1 (64 j each)
    #pragma unroll
    for (int pc = 0; pc < 2; pc++) {
        if (tid < 128) {
            int row = tid >> 1, half = tid & 1;
            CP16(smb + KS_OFF + pc*3072 + row*48 + half*16,
                 g_kt + ((size_t)(b*HWN) + pc*64 + row)*RR + half*8);
        }
        #pragma unroll
        for (int v = 0; v < 4; v++) {
            int row = v*64 + (tid >> 2);
            int c16 = tid & 3;
            CP16(smb + VS_OFF + pc*20480 + row*80 + c16*16,
                 g_v8 + ((size_t)(b*CC + row))*HWN + pc*64 + c16*16);
        }
        CP_COMMIT();
    }

    float acc[4][4][4];
    #pragma unroll
    for (int mi = 0; mi < 4; mi++)
        #pragma unroll
        for (int ni = 0; ni < 4; ni++)
            #pragma unroll
            for (int e = 0; e < 4; e++) acc[mi][ni][e] = 0.f;
    float rs0 = 0.f, rs1 = 0.f;

    #pragma unroll 1
    for (int jc = 0; jc < NCHUNK; jc++) {
        int buf = jc & 1;
        if (jc == NCHUNK-1) { CP_WAIT(0); } else { CP_WAIT(1); }
        __syncthreads();

        // ---- scores: warp (wm, wnj) computes S[16 i x 32 j] (bf16 mma) ----
        uint32_t aq[4];
        LDSM4(aq[0], aq[1], aq[2], aq[3],
              smb + QS_OFF + (wm*16 + frow)*48 + fcolh*2);
        uint32_t bk[2][4];
        #pragma unroll
        for (int nj = 0; nj < 2; nj++) {
            LDSM4(bk[nj][0], bk[nj][1], bk[nj][2], bk[nj][3],
                  smb + KS_OFF + buf*3072 + (wnj*32 + nj*16 + frow)*48 + fcolh*2);
        }
        float sacc[4][4];
        #pragma unroll
        for (int t = 0; t < 4; t++)
            #pragma unroll
            for (int e = 0; e < 4; e++) sacc[t][e] = 0.f;
        #pragma unroll
        for (int t = 0; t < 4; t++)
            MMA16816(sacc[t], aq, bk[t>>1][t&1], bk[t>>1][(t&1)+2]);

        // ---- exp(s-3) -> fp8 Es, row sums from DECODED fp8 ----
        #pragma unroll
        for (int t = 0; t < 4; t++) {
            int col = wnj*32 + t*8 + qc;
            int row = wm*16 + qr;
            uint16_t p01 = pk_e4m3(__expf(sacc[t][0] - 3.f), __expf(sacc[t][1] - 3.f));
            uint16_t p23 = pk_e4m3(__expf(sacc[t][2] - 3.f), __expf(sacc[t][3] - 3.f));
            asm volatile("st.shared.u16 [%0], %1;"
                :: "r"(smb + ES_OFF + row*80 + col), "h"(p01) : "memory");
            asm volatile("st.shared.u16 [%0], %1;"
                :: "r"(smb + ES_OFF + (row+8)*80 + col), "h"(p23) : "memory");
            float2 f01 = de_e4m3(p01);
            float2 f23 = de_e4m3(p23);
            rs0 += f01.x + f01.y;
            rs1 += f23.x + f23.y;
        }
        __syncthreads();

        // ---- AV (fp8): warp (wc, wi) D[64c x 32i] += V[64c x 64j] * E[32i x 64j]^T ----
        #pragma unroll
        for (int kh = 0; kh < 2; kh++) {
            uint32_t av[4][4];
            #pragma unroll
            for (int mi = 0; mi < 4; mi++) {
                LDSM4(av[mi][0], av[mi][1], av[mi][2], av[mi][3],
                      smb + VS_OFF + buf*20480 + (wc*64 + mi*16 + frow)*80 + kh*32 + fcolh*2);
            }
            uint32_t be[2][4];
            #pragma unroll
            for (int nj = 0; nj < 2; nj++) {
                LDSM4(be[nj][0], be[nj][1], be[nj][2], be[nj][3],
                      smb + ES_OFF + (wi*32 + nj*16 + frow)*80 + kh*32 + fcolh*2);
            }
            #pragma unroll
            for (int mi = 0; mi < 4; mi++)
                #pragma unroll
                for (int ni = 0; ni < 4; ni++)
                    MMAFP8(acc[mi][ni], av[mi], be[ni>>1][ni&1], be[ni>>1][(ni&1)+2]);
        }
        __syncthreads();

        // ---- prefetch chunk jc+2 into freed buf ----
        int pf = jc + 2;
        if (pf < NCHUNK) {
            if (tid < 128) {
                int row = tid >> 1, half = tid & 1;
                CP16(smb + KS_OFF + buf*3072 + row*48 + half*16,
                     g_kt + ((size_t)(b*HWN) + pf*64 + row)*RR + half*8);
            }
            #pragma unroll
            for (int v = 0; v < 4; v++) {
                int row = v*64 + (tid >> 2);
                int c16 = tid & 3;
                CP16(smb + VS_OFF + buf*20480 + row*80 + c16*16,
                     g_v8 + ((size_t)(b*CC + row))*HWN + pf*64 + c16*16);
            }
            CP_COMMIT();
        }
    }

    // ---- row sums: combine j-halves, invert ----
    rs0 += __shfl_xor_sync(0xffffffffu, rs0, 1);
    rs0 += __shfl_xor_sync(0xffffffffu, rs0, 2);
    rs1 += __shfl_xor_sync(0xffffffffu, rs1, 1);
    rs1 += __shfl_xor_sync(0xffffffffu, rs1, 2);
    float* rs2 = (float*)(smx + RS2_OFF);
    float* inv = (float*)(smx + INV_OFF);
    if ((lane & 3) == 0) {
        rs2[wnj*64 + wm*16 + qr    ] = rs0;
        rs2[wnj*64 + wm*16 + qr + 8] = rs1;
    }
    __syncthreads();
    if (tid < 64) inv[tid] = 1.f / (rs2[tid] + rs2[64 + tid]);
    __syncthreads();

    // ---- epilogue: out = gamma * D * inv[i] + xg ----
    float gm = gamma[0];
    #pragma unroll
    for (int ni = 0; ni < 4; ni++) {
        int iloc = wi*32 + ni*8 + qc;
        float inv0 = inv[iloc], inv1 = inv[iloc + 1];
        #pragma unroll
        for (int mi = 0; mi < 4; mi++) {
            #pragma unroll
            for (int h = 0; h < 2; h++) {
                int c = wc*64 + mi*16 + qr + h*8;
                size_t base = ((size_t)(b*CC + c))*HWN + i0 + iloc;
                float2 xgv = *(const float2*)(g_xg + base);
                float2 o;
                o.x = gm * acc[mi][ni][2*h+0] * inv0 + xgv.x;
                o.y = gm * acc[mi][ni][2*h+1] * inv1 + xgv.y;
                *(float2*)(out + base) = o;
            }
        }
    }
}

// ---------------- launch ----------------
extern "C" void kernel_launch(void* const* d_in, const int* in_sizes, int n_in,
                              void* d_out, int out_size) {
    const float* x     = (const float*)d_in[0];
    const float* ca_w1 = (const float*)d_in[1];
    const float* ca_w2 = (const float*)d_in[2];
    const float* q_w   = (const float*)d_in[3];
    const float* q_b   = (const float*)d_in[4];
    const float* k_w   = (const float*)d_in[5];
    const float* k_b   = (const float*)d_in[6];
    const float* v_w   = (const float*)d_in[7];
    const float* v_b   = (const float*)d_in[8];
    const float* gamma = (const float*)d_in[9];
    float* out = (float*)d_out;

    cudaFuncSetAttribute(k_attn, cudaFuncAttributeMaxDynamicSharedMemorySize, ATTN_SMEM);

    k_pool  <<<BB*CC, 256>>>(x);
    k_wpack <<<MPAD, 256>>>(v_w, q_w, k_w, v_b, q_b, k_b);
    k_gate  <<<BB, 256>>>(ca_w1, ca_w2);
    k_xgt   <<<dim3(HWN/32, CC/32, BB), 256>>>(x);
    k_qkv   <<<dim3(HWN/128, MPAD/128, BB), 256>>>();
    k_attn  <<<dim3(HWN/64, BB), 256, ATTN_SMEM>>>(gamma, out);
}

// round 17
// speedup vs baseline: 1.3531x; 1.0526x over previous
#include <cuda_runtime.h>
#include <cuda_bf16.h>
#include <cstdint>
#include <math.h>

#define BB 8
#define CC 256
#define HWN 4096
#define RR 16
#define MQKV 288   // 256 v rows + 16 q rows + 16 k rows
#define MPAD 384   // padded to 3 tiles of 128

// ---------------- scratch (device globals; no allocations) ----------------
__device__ float g_avg[BB*CC];
__device__ float g_mx [BB*CC];
__device__ float g_gate[BB*CC];
__device__ __nv_bfloat16 g_xgt[(size_t)BB*HWN*CC];    // bf16 gated input, transposed [b][n][c]
__device__ __nv_bfloat16 g_wh[MPAD*CC];               // packed bf16 [v;q;k;pad] weights
__device__ float g_bcat[MPAD];
__device__ __nv_bfloat16 g_qt[(size_t)BB*HWN*RR];     // q transposed [b][n][r]
__device__ __nv_bfloat16 g_kt[(size_t)BB*HWN*RR];
__device__ uint8_t g_v8[(size_t)BB*CC*HWN];           // V in fp8 e4m3 [b][c][n]

// ---------------- asm helpers ----------------
__device__ __forceinline__ unsigned int sptr(const void* p) {
    return (unsigned int)__cvta_generic_to_shared(p);
}
#define CP16(dst, src) asm volatile("cp.async.cg.shared.global [%0], [%1], 16;\n" :: "r"(dst), "l"(src))
#define CP16P(dst, src) asm volatile("cp.async.cg.shared.global [%0], [%1], 16;\n" :: "r"(sptr(dst)), "l"(src))
#define CP_COMMIT()    asm volatile("cp.async.commit_group;\n")
#define CP_WAIT(n)     asm volatile("cp.async.wait_group %0;\n" :: "n"(n))
#define LDSM4(r0,r1,r2,r3,addr) \
    asm volatile("ldmatrix.sync.aligned.m8n8.x4.shared.b16 {%0,%1,%2,%3}, [%4];\n" \
        : "=r"(r0),"=r"(r1),"=r"(r2),"=r"(r3) : "r"(addr))
#define MMA16816(d,a,b0,b1) \
    asm volatile("mma.sync.aligned.m16n8k16.row.col.f32.bf16.bf16.f32 " \
        "{%0,%1,%2,%3}, {%4,%5,%6,%7}, {%8,%9}, {%0,%1,%2,%3};\n" \
        : "+f"(d[0]),"+f"(d[1]),"+f"(d[2]),"+f"(d[3]) \
        : "r"(a[0]),"r"(a[1]),"r"(a[2]),"r"(a[3]), "r"(b0),"r"(b1))
#define MMAFP8(d,a,b0,b1) \
    asm volatile("mma.sync.aligned.m16n8k32.row.col.f32.e4m3.e4m3.f32 " \
        "{%0,%1,%2,%3}, {%4,%5,%6,%7}, {%8,%9}, {%0,%1,%2,%3};\n" \
        : "+f"(d[0]),"+f"(d[1]),"+f"(d[2]),"+f"(d[3]) \
        : "r"(a[0]),"r"(a[1]),"r"(a[2]),"r"(a[3]), "r"(b0),"r"(b1))

// pack two f32 -> e4m3x2 (lo at low byte), decode back via f16x2
__device__ __forceinline__ uint16_t pk_e4m3(float lo, float hi) {
    uint16_t r;
    asm("cvt.rn.satfinite.e4m3x2.f32 %0, %1, %2;" : "=h"(r) : "f"(hi), "f"(lo));
    return r;
}
__device__ __forceinline__ float2 de_e4m3(uint16_t h) {
    uint32_t hf;
    asm("cvt.rn.f16x2.e4m3x2 %0, %1;" : "=r"(hf) : "h"(h));
    __half2 h2 = *(__half2*)&hf;
    return __half22float2(h2);
}

// ---------------- 1) avg+max pool over HW per (b,c) ----------------
__global__ __launch_bounds__(256) void k_pool(const float* __restrict__ x) {
    int bc = blockIdx.x;
    const float4* p = (const float4*)(x + (size_t)bc * HWN);
    float s = 0.f, m = -1e30f;
    for (int i = threadIdx.x; i < HWN/4; i += 256) {
        float4 v = p[i];
        s += v.x + v.y + v.z + v.w;
        m = fmaxf(m, fmaxf(fmaxf(v.x, v.y), fmaxf(v.z, v.w)));
    }
    __shared__ float ss[8], sm[8];
    for (int o = 16; o; o >>= 1) {
        s += __shfl_xor_sync(0xffffffffu, s, o);
        m = fmaxf(m, __shfl_xor_sync(0xffffffffu, m, o));
    }
    if ((threadIdx.x & 31) == 0) { ss[threadIdx.x >> 5] = s; sm[threadIdx.x >> 5] = m; }
    __syncthreads();
    if (threadIdx.x == 0) {
        float S = 0.f, M = -1e30f;
        for (int w = 0; w < 8; w++) { S += ss[w]; M = fmaxf(M, sm[w]); }
        g_avg[bc] = S * (1.f / HWN);
        g_mx[bc]  = M;
    }
}

// ---------------- 2) SE gate ----------------
__global__ __launch_bounds__(256) void k_gate(const float* __restrict__ w1,
                                              const float* __restrict__ w2) {
    int b = blockIdx.x, t = threadIdx.x;
    __shared__ float sa[CC], sx[CC], h[RR];
    sa[t] = g_avg[b*CC + t];
    sx[t] = g_mx [b*CC + t];
    __syncthreads();
    if (t < RR) {
        float da = 0.f, dm = 0.f;
        const float* w = w1 + t*CC;
        for (int c = 0; c < CC; c++) { da += w[c]*sa[c]; dm += w[c]*sx[c]; }
        h[t] = fmaxf(da, 0.f) + fmaxf(dm, 0.f);
    }
    __syncthreads();
    float g = 0.f;
    const float* w = w2 + t*RR;
    #pragma unroll
    for (int r = 0; r < RR; r++) g += w[r]*h[r];
    g_gate[b*CC + t] = 1.f / (1.f + __expf(-g));
}

// ---------------- 3) pack [v;q;k] weights -> bf16 (padded), biases fp32 ----------------
__global__ __launch_bounds__(256) void k_wpack(const float* __restrict__ vw,
                                               const float* __restrict__ qw,
                                               const float* __restrict__ kw,
                                               const float* __restrict__ vb,
                                               const float* __restrict__ qb,
                                               const float* __restrict__ kb) {
    int o = blockIdx.x, t = threadIdx.x;
    float val = 0.f, bias = 0.f;
    if (o < CC)            { val = vw[o*CC + t];          bias = vb[o]; }
    else if (o < CC + RR)  { val = qw[(o-CC)*CC + t];     bias = qb[o-CC]; }
    else if (o < MQKV)     { val = kw[(o-CC-RR)*CC + t];  bias = kb[o-CC-RR]; }
    g_wh[o*CC + t] = __float2bfloat16(val);
    if (t == 0) g_bcat[o] = bias;
}

// ---------------- 4) transposed bf16 xgt only (no fp32 xg write) ----------------
__global__ __launch_bounds__(256) void k_xgt(const float* __restrict__ x) {
    int b = blockIdx.z, c0 = blockIdx.y*32, n0 = blockIdx.x*32;
    __shared__ float t[32][33];
    int tid = threadIdx.x;
    int tx = tid & 31, ty = tid >> 5;
    const float* xb = x + ((size_t)(b*CC + c0))*HWN + n0;
    #pragma unroll
    for (int r = ty; r < 32; r += 8) {
        float g = g_gate[b*CC + c0 + r];
        t[r][tx] = xb[(size_t)r*HWN + tx] * g;
    }
    __syncthreads();
    __nv_bfloat16* dst = g_xgt + ((size_t)(b*HWN + n0))*CC + c0;
    int r2 = tid >> 3, ch = (tid & 7) * 4;
    union { __nv_bfloat162 h[2]; uint2 u; } pk;
    pk.h[0] = __floats2bfloat162_rn(t[ch+0][r2], t[ch+1][r2]);
    pk.h[1] = __floats2bfloat162_rn(t[ch+2][r2], t[ch+3][r2]);
    *(uint2*)(dst + (size_t)r2*CC + ch) = pk.u;
}

// ---------------- 5) fused QKV projection, bf16 mma; V out in fp8 ----------------
__global__ __launch_bounds__(256) void k_qkv() {
    int b  = blockIdx.z;
    int o0 = blockIdx.y * 128;
    int n0 = blockIdx.x * 128;
    __shared__ __align__(16) __nv_bfloat16 As[2][128][40];
    __shared__ __align__(16) __nv_bfloat16 Bs[2][128][40];

    int tid = threadIdx.x, lane = tid & 31, wid = tid >> 5;
    int wm = wid >> 2, wn = wid & 3;

    const __nv_bfloat16* Ab = g_wh + (size_t)o0 * CC;
    const __nv_bfloat16* Bb = g_xgt + ((size_t)(b*HWN) + n0) * CC;

    int lr = tid >> 2;
    int lc = (tid & 3) * 8;

    float acc[4][4][4];
    #pragma unroll
    for (int mi = 0; mi < 4; mi++)
        #pragma unroll
        for (int ni = 0; ni < 4; ni++)
            #pragma unroll
            for (int e = 0; e < 4; e++) acc[mi][ni][e] = 0.f;

    #pragma unroll
    for (int pc = 0; pc < 2; pc++) {
        int k0 = pc * 32;
        CP16P(&As[pc][lr     ][lc], Ab + (size_t)(lr     )*CC + k0 + lc);
        CP16P(&As[pc][lr + 64][lc], Ab + (size_t)(lr + 64)*CC + k0 + lc);
        CP16P(&Bs[pc][lr     ][lc], Bb + (size_t)(lr     )*CC + k0 + lc);
        CP16P(&Bs[pc][lr + 64][lc], Bb + (size_t)(lr + 64)*CC + k0 + lc);
        CP_COMMIT();
    }

    #pragma unroll 1
    for (int it = 0; it < 8; it++) {
        int buf = it & 1;
        if (it == 7) { CP_WAIT(0); } else { CP_WAIT(1); }
        __syncthreads();
        #pragma unroll
        for (int ks = 0; ks < 2; ks++) {
            int k = ks * 16;
            int frow = lane & 15;
            int fcol = k + ((lane >> 4) << 3);
            uint32_t a[4][4];
            #pragma unroll
            for (int mi = 0; mi < 4; mi++) {
                unsigned int ad = sptr(&As[buf][wm*64 + mi*16 + frow][fcol]);
                LDSM4(a[mi][0], a[mi][1], a[mi][2], a[mi][3], ad);
            }
            uint32_t bf[2][4];
            #pragma unroll
            for (int nj = 0; nj < 2; nj++) {
                unsigned int ad = sptr(&Bs[buf][wn*32 + nj*16 + frow][fcol]);
                LDSM4(bf[nj][0], bf[nj][1], bf[nj][2], bf[nj][3], ad);
            }
            #pragma unroll
            for (int mi = 0; mi < 4; mi++)
                #pragma unroll
                for (int ni = 0; ni < 4; ni++) {
                    int nj = ni >> 1, h = ni & 1;
                    MMA16816(acc[mi][ni], a[mi], bf[nj][h], bf[nj][h+2]);
                }
        }
        __syncthreads();
        if (it + 2 < 8) {
            int k0 = (it + 2) * 32;
            CP16P(&As[buf][lr     ][lc], Ab + (size_t)(lr     )*CC + k0 + lc);
            CP16P(&As[buf][lr + 64][lc], Ab + (size_t)(lr + 64)*CC + k0 + lc);
            CP16P(&Bs[buf][lr     ][lc], Bb + (size_t)(lr     )*CC + k0 + lc);
            CP16P(&Bs[buf][lr + 64][lc], Bb + (size_t)(lr + 64)*CC + k0 + lc);
            CP_COMMIT();
        }
    }

    int qr = lane >> 2, qc = (lane & 3) * 2;
    #pragma unroll
    for (int mi = 0; mi < 4; mi++) {
        #pragma unroll
        for (int h = 0; h < 2; h++) {
            int r = o0 + wm*64 + mi*16 + qr + h*8;
            if (r >= MQKV) continue;
            float bias = g_bcat[r];
            if (r < CC) {
                uint8_t* dst = g_v8 + ((size_t)(b*CC + r)) * HWN;
                #pragma unroll
                for (int ni = 0; ni < 4; ni++) {
                    int icol = n0 + wn*32 + ni*8 + qc;
                    *(uint16_t*)(dst + icol) =
                        pk_e4m3(acc[mi][ni][2*h+0] + bias, acc[mi][ni][2*h+1] + bias);
                }
            } else {
                __nv_bfloat16* dst = (r < CC + RR) ? g_qt : g_kt;
                int rr = (r < CC + RR) ? (r - CC) : (r - CC - RR);
                #pragma unroll
                for (int ni = 0; ni < 4; ni++) {
                    int icol = n0 + wn*32 + ni*8 + qc;
                    dst[((size_t)(b*HWN) + icol    )*RR + rr] = __float2bfloat16(acc[mi][ni][2*h+0] + bias);
                    dst[((size_t)(b*HWN) + icol + 1)*RR + rr] = __float2bfloat16(acc[mi][ni][2*h+1] + bias);
                }
            }
        }
    }
}

// ---------------- 6) FUSED attention, fp8 AV, chunk 64, occupancy 2 --------------------
// epilogue recomputes xg = x * gate on the fly (g_xg eliminated).
// smem:
//   Qs   @ 0     : 64 x 48B            = 3072
//   Ks   @ 3072  : 2 x 64 x 48B        = 6144
//   Es   @ 9216  : 64 x 80B (fp8)      = 5120
//   Vs   @ 14336 : 2 x 256 x 80B (fp8) = 40960
//   rs2  @ 55296 : 2 x 64 f32          = 512
//   inv  @ 55808 : 64 f32              = 256
//   gates@ 56064 : 256 f32             = 1024
#define QS_OFF 0
#define KS_OFF 3072
#define ES_OFF 9216
#define VS_OFF 14336
#define RS2_OFF 55296
#define INV_OFF 55808
#define GT_OFF 56064
#define ATTN_SMEM 57088
#define NCHUNK 64            // 4096 / 64

__global__ __launch_bounds__(256, 2) void k_attn(const float* __restrict__ gamma,
                                                 const float* __restrict__ x,
                                                 float* __restrict__ out) {
    extern __shared__ __align__(16) char smx[];
    uint32_t smb = sptr(smx);
    int tid = threadIdx.x, lane = tid & 31, wid = tid >> 5;
    int b = blockIdx.y;
    int i0 = blockIdx.x * 64;

    int qr = lane >> 2, qc = (lane & 3) * 2;
    int frow = lane & 15, fcolh = (lane >> 4) << 3;

    int wm = wid >> 1, wnj = wid & 1;     // score phase: 4 i-groups(16) x 2 j-halves(32)
    int wc = wid & 3,  wi  = wid >> 2;    // AV phase: 4 c-groups(64) x 2 i-halves(32)

    if (tid < 128) {
        int row = tid >> 1, half = tid & 1;
        *(uint4*)(smx + QS_OFF + row*48 + half*16) =
            *(const uint4*)(g_qt + ((size_t)(b*HWN) + i0 + row)*RR + half*8);
    }
    ((float*)(smx + GT_OFF))[tid] = g_gate[b*CC + tid];

    // prologue: K + V for chunks 0, 1 (64 j each)
    #pragma unroll
    for (int pc = 0; pc < 2; pc++) {
        if (tid < 128) {
            int row = tid >> 1, half = tid & 1;
            CP16(smb + KS_OFF + pc*3072 + row*48 + half*16,
                 g_kt + ((size_t)(b*HWN) + pc*64 + row)*RR + half*8);
        }
        #pragma unroll
        for (int v = 0; v < 4; v++) {
            int row = v*64 + (tid >> 2);
            int c16 = tid & 3;
            CP16(smb + VS_OFF + pc*20480 + row*80 + c16*16,
                 g_v8 + ((size_t)(b*CC + row))*HWN + pc*64 + c16*16);
        }
        CP_COMMIT();
    }

    // Q fragment is loop-invariant: load once after Qs is visible
    __syncthreads();
    uint32_t aq[4];
    LDSM4(aq[0], aq[1], aq[2], aq[3],
          smb + QS_OFF + (wm*16 + frow)*48 + fcolh*2);

    float acc[4][4][4];
    #pragma unroll
    for (int mi = 0; mi < 4; mi++)
        #pragma unroll
        for (int ni = 0; ni < 4; ni++)
            #pragma unroll
            for (int e = 0; e < 4; e++) acc[mi][ni][e] = 0.f;
    float rs0 = 0.f, rs1 = 0.f;

    #pragma unroll 1
    for (int jc = 0; jc < NCHUNK; jc++) {
        int buf = jc & 1;
        if (jc == NCHUNK-1) { CP_WAIT(0); } else { CP_WAIT(1); }
        __syncthreads();

        // ---- scores: warp (wm, wnj) computes S[16 i x 32 j] (bf16 mma) ----
        uint32_t bk[2][4];
        #pragma unroll
        for (int nj = 0; nj < 2; nj++) {
            LDSM4(bk[nj][0], bk[nj][1], bk[nj][2], bk[nj][3],
                  smb + KS_OFF + buf*3072 + (wnj*32 + nj*16 + frow)*48 + fcolh*2);
        }
        float sacc[4][4];
        #pragma unroll
        for (int t = 0; t < 4; t++)
            #pragma unroll
            for (int e = 0; e < 4; e++) sacc[t][e] = 0.f;
        #pragma unroll
        for (int t = 0; t < 4; t++)
            MMA16816(sacc[t], aq, bk[t>>1][t&1], bk[t>>1][(t&1)+2]);

        // ---- exp(s-3) -> fp8 Es, row sums from DECODED fp8 ----
        #pragma unroll
        for (int t = 0; t < 4; t++) {
            int col = wnj*32 + t*8 + qc;
            int row = wm*16 + qr;
            uint16_t p01 = pk_e4m3(__expf(sacc[t][0] - 3.f), __expf(sacc[t][1] - 3.f));
            uint16_t p23 = pk_e4m3(__expf(sacc[t][2] - 3.f), __expf(sacc[t][3] - 3.f));
            asm volatile("st.shared.u16 [%0], %1;"
                :: "r"(smb + ES_OFF + row*80 + col), "h"(p01) : "memory");
            asm volatile("st.shared.u16 [%0], %1;"
                :: "r"(smb + ES_OFF + (row+8)*80 + col), "h"(p23) : "memory");
            float2 f01 = de_e4m3(p01);
            float2 f23 = de_e4m3(p23);
            rs0 += f01.x + f01.y;
            rs1 += f23.x + f23.y;
        }
        __syncthreads();

        // ---- AV (fp8): warp (wc, wi) D[64c x 32i] += V[64c x 64j] * E[32i x 64j]^T ----
        #pragma unroll
        for (int kh = 0; kh < 2; kh++) {
            uint32_t av[4][4];
            #pragma unroll
            for (int mi = 0; mi < 4; mi++) {
                LDSM4(av[mi][0], av[mi][1], av[mi][2], av[mi][3],
                      smb + VS_OFF + buf*20480 + (wc*64 + mi*16 + frow)*80 + kh*32 + fcolh*2);
            }
            uint32_t be[2][4];
            #pragma unroll
            for (int nj = 0; nj < 2; nj++) {
                LDSM4(be[nj][0], be[nj][1], be[nj][2], be[nj][3],
                      smb + ES_OFF + (wi*32 + nj*16 + frow)*80 + kh*32 + fcolh*2);
            }
            #pragma unroll
            for (int mi = 0; mi < 4; mi++)
                #pragma unroll
                for (int ni = 0; ni < 4; ni++)
                    MMAFP8(acc[mi][ni], av[mi], be[ni>>1][ni&1], be[ni>>1][(ni&1)+2]);
        }
        __syncthreads();

        // ---- prefetch chunk jc+2 into freed buf ----
        int pf = jc + 2;
        if (pf < NCHUNK) {
            if (tid < 128) {
                int row = tid >> 1, half = tid & 1;
                CP16(smb + KS_OFF + buf*3072 + row*48 + half*16,
                     g_kt + ((size_t)(b*HWN) + pf*64 + row)*RR + half*8);
            }
            #pragma unroll
            for (int v = 0; v < 4; v++) {
                int row = v*64 + (tid >> 2);
                int c16 = tid & 3;
                CP16(smb + VS_OFF + buf*20480 + row*80 + c16*16,
                     g_v8 + ((size_t)(b*CC + row))*HWN + pf*64 + c16*16);
            }
            CP_COMMIT();
        }
    }

    // ---- row sums: combine j-halves, invert ----
    rs0 += __shfl_xor_sync(0xffffffffu, rs0, 1);
    rs0 += __shfl_xor_sync(0xffffffffu, rs0, 2);
    rs1 += __shfl_xor_sync(0xffffffffu, rs1, 1);
    rs1 += __shfl_xor_sync(0xffffffffu, rs1, 2);
    float* rs2 = (float*)(smx + RS2_OFF);
    float* inv = (float*)(smx + INV_OFF);
    if ((lane & 3) == 0) {
        rs2[wnj*64 + wm*16 + qr    ] = rs0;
        rs2[wnj*64 + wm*16 + qr + 8] = rs1;
    }
    __syncthreads();
    if (tid < 64) inv[tid] = 1.f / (rs2[tid] + rs2[64 + tid]);
    __syncthreads();

    // ---- epilogue: out = gamma * D * inv[i] + x * gate[c] ----
    float gm = gamma[0];
    const float* gates = (const float*)(smx + GT_OFF);
    #pragma unroll
    for (int ni = 0; ni < 4; ni++) {
        int iloc = wi*32 + ni*8 + qc;
        float inv0 = inv[iloc], inv1 = inv[iloc + 1];
        #pragma unroll
        for (int mi = 0; mi < 4; mi++) {
            #pragma unroll
            for (int h = 0; h < 2; h++) {
                int c = wc*64 + mi*16 + qr + h*8;
                float gt = gates[c];
                size_t base = ((size_t)(b*CC + c))*HWN + i0 + iloc;
                float2 xv = *(const float2*)(x + base);
                float2 o;
                o.x = gm * acc[mi][ni][2*h+0] * inv0 + xv.x * gt;
                o.y = gm * acc[mi][ni][2*h+1] * inv1 + xv.y * gt;
                *(float2*)(out + base) = o;
            }
        }
    }
}

// ---------------- launch ----------------
extern "C" void kernel_launch(void* const* d_in, const int* in_sizes, int n_in,
                              void* d_out, int out_size) {
    const float* x     = (const float*)d_in[0];
    const float* ca_w1 = (const float*)d_in[1];
    const float* ca_w2 = (const float*)d_in[2];
    const float* q_w   = (const float*)d_in[3];
    const float* q_b   = (const float*)d_in[4];
    const float* k_w   = (const float*)d_in[5];
    const float* k_b   = (const float*)d_in[6];
    const float* v_w   = (const float*)d_in[7];
    const float* v_b   = (const float*)d_in[8];
    const float* gamma = (const float*)d_in[9];
    float* out = (float*)d_out;

    cudaFuncSetAttribute(k_attn, cudaFuncAttributeMaxDynamicSharedMemorySize, ATTN_SMEM);

    k_pool  <<<BB*CC, 256>>>(x);
    k_wpack <<<MPAD, 256>>>(v_w, q_w, k_w, v_b, q_b, k_b);
    k_gate  <<<BB, 256>>>(ca_w1, ca_w2);
    k_xgt   <<<dim3(HWN/32, CC/32, BB), 256>>>(x);
    k_qkv   <<<dim3(HWN/128, MPAD/128, BB), 256>>>();
    k_attn  <<<dim3(HWN/64, BB), 256, ATTN_SMEM>>>(gamma, x, out);
}